// round 13
// baseline (speedup 1.0000x reference)
#include <cuda_runtime.h>
#include <cuda_fp16.h>
#include <math.h>
#include <stdint.h>

#define NB   4
#define LSEQ 2048
#define EMB  1024
#define NH   16
#define HD   64
#define BHN  (NB*NH)
// Q pre-scale: (1/sqrt(EMB)) * log2(e)  -> scores come out in log2 domain
#define QS   (0.04508422f)
#define HONES 0x3C003C00u     // fp16x2 {1.0, 1.0}

// ---------------- scratch ----------------
__device__ __half g_qh[BHN*LSEQ*HD];          // fp16 [bh][l][d] (pre-scaled, linear)
__device__ __half g_kh[BHN*LSEQ*HD];          // fp16 [bh][l][d] XOR-swizzled chunks
__device__ __half g_vh[BHN*LSEQ*HD];          // fp16, swizzled
// attention out, TILED fp16: [mb 64][kb 32][128 rows][40 half (32 data + 8 pad)]
__device__ __half g_ao_t[64*32*128*40];
// Wo, TILED fp16: [nb 8][kb 32][128][40]
__device__ __half g_wo_t[8*32*128*40];

__device__ __forceinline__ uint32_t cvt_h2(float a, float b) {   // a -> low half
    uint32_t r; asm("cvt.rn.f16x2.f32 %0, %1, %2;" : "=r"(r) : "f"(b), "f"(a)); return r;
}
__device__ __forceinline__ uint32_t ex2_h2(uint32_t s) {
    uint32_t r; asm("ex2.approx.f16x2 %0, %1;" : "=r"(r) : "r"(s)); return r;
}
__device__ __forceinline__ uint32_t smem_u32(const void* p) {
    uint32_t a;
    asm("{ .reg .u64 t; cvta.to.shared.u64 t, %1; cvt.u32.u64 %0, t; }" : "=r"(a) : "l"(p));
    return a;
}
__device__ __forceinline__ void mma16816h(float* c, const uint32_t* a,
                                          uint32_t b0, uint32_t b1) {
    asm volatile("mma.sync.aligned.m16n8k16.row.col.f32.f16.f16.f32 "
        "{%0,%1,%2,%3}, {%4,%5,%6,%7}, {%8,%9}, {%0,%1,%2,%3};"
        : "+f"(c[0]), "+f"(c[1]), "+f"(c[2]), "+f"(c[3])
        : "r"(a[0]), "r"(a[1]), "r"(a[2]), "r"(a[3]), "r"(b0), "r"(b1));
}
#define LDMX4(r0, r1, r2, r3, addr) \
    asm volatile("ldmatrix.sync.aligned.m8n8.x4.shared.b16 {%0,%1,%2,%3}, [%4];" \
        : "=r"(r0), "=r"(r1), "=r"(r2), "=r"(r3) : "r"(addr))
#define LDMX4T(r0, r1, r2, r3, addr) \
    asm volatile("ldmatrix.sync.aligned.m8n8.x4.trans.shared.b16 {%0,%1,%2,%3}, [%4];" \
        : "=r"(r0), "=r"(r1), "=r"(r2), "=r"(r3) : "r"(addr))

#define CP_BULK(dst, src, bytes, mbar) \
    asm volatile("cp.async.bulk.shared::cta.global.mbarrier::complete_tx::bytes [%0], [%1], %2, [%3];" \
        :: "r"(dst), "l"(src), "r"((uint32_t)(bytes)), "r"(mbar) : "memory")
#define MBAR_INIT(a, c) \
    asm volatile("mbarrier.init.shared.b64 [%0], %1;" :: "r"(a), "r"((uint32_t)(c)) : "memory")
#define MBAR_EXPECT_TX(a, tx) \
    asm volatile("mbarrier.arrive.expect_tx.shared.b64 _, [%0], %1;" :: "r"(a), "r"((uint32_t)(tx)) : "memory")
#define MBAR_WAIT(mbar, par) do {                                              \
    uint32_t _m = (mbar), _p = (par), _d;                                      \
    asm volatile("{\n\t.reg .pred p;\n\t"                                      \
        "mbarrier.try_wait.parity.acquire.cta.shared::cta.b64 p, [%1], %2;\n\t"\
        "selp.b32 %0, 1, 0, p;\n\t}" : "=r"(_d) : "r"(_m), "r"(_p) : "memory");\
    if (!_d) {                                                                 \
        asm volatile("{\n\t.reg .pred P1;\n\t"                                 \
            "W_%=:\n\t"                                                        \
            "mbarrier.try_wait.parity.acquire.cta.shared::cta.b64 P1, [%0], %1, 0x989680;\n\t" \
            "@P1 bra.uni D_%=;\n\t"                                            \
            "bra.uni W_%=;\n\t"                                                \
            "D_%=:\n\t}" :: "r"(_m), "r"(_p) : "memory");                      \
    }                                                                          \
} while (0)

// ---------------------------------------------------------------------------
// Kernel 1: QKV projection on HMMA + (z=1) Wo tiling, fused in one launch.
// ---------------------------------------------------------------------------
#define QKV_SMX 24576
#define QKV_SMT 57344

__global__ void __launch_bounds__(256) qkv_mma_kernel(
    const float* __restrict__ q_in, const float* __restrict__ k_in,
    const float* __restrict__ v_in,
    const float* __restrict__ Wq, const float* __restrict__ Wk,
    const float* __restrict__ Wv, const float* __restrict__ Wo)
{
    const int tid = threadIdx.x;

    // ---- z=1 blocks: Wo fp32 -> fp16 TILED [nb][kb][128][40] ----
    if (blockIdx.z == 1) {
        const int bid = blockIdx.y * 8 + blockIdx.x;   // 0..511
#pragma unroll
        for (int u = 0; u < 2; u++) {
            const int i4 = (bid * 512 + u * 256 + tid) * 4;
            const int e = i4 >> 10, k = i4 & 1023;
            float4 w = *reinterpret_cast<const float4*>(Wo + i4);
            const int nb = e >> 7, er = e & 127, kb = k >> 5, c = k & 31;
            const size_t base = ((size_t)(nb * 32 + kb) * 128 + er) * 40 + c;
            uint32_t* oh = reinterpret_cast<uint32_t*>(g_wo_t + base);
            oh[0] = cvt_h2(w.x, w.y); oh[1] = cvt_h2(w.z, w.w);
        }
        return;
    }

    extern __shared__ char sm[];
    const uint32_t smb = smem_u32(sm);
    const int wid = tid >> 5, lane = tid & 31;
    const int g = lane >> 2, t = lane & 3;
    const int lm = lane >> 3, lr = lane & 7;
    const int bh = blockIdx.y;
    const int tile = blockIdx.x;
    const int n = bh >> 4, h = bh & 15;

    const float* Ws[3] = {Wq, Wk, Wv};
#pragma unroll
    for (int w = 0; w < 3; w++) {
#pragma unroll
        for (int u = 0; u < 2; u++) {
            int cl = tid + u * 256;
            int row = cl >> 3, c = cl & 7;
            float4 f0 = reinterpret_cast<const float4*>(Ws[w])[row * 16 + c * 2];
            float4 f1 = reinterpret_cast<const float4*>(Ws[w])[row * 16 + c * 2 + 1];
            uint4 pk;
            pk.x = cvt_h2(f0.x, f0.y); pk.y = cvt_h2(f0.z, f0.w);
            pk.z = cvt_h2(f1.x, f1.y); pk.w = cvt_h2(f1.z, f1.w);
            *reinterpret_cast<uint4*>(sm + w * 8192 + row * 128 + ((c ^ (row & 7)) << 4)) = pk;
        }
    }

    const float* ins[3] = {q_in, k_in, v_in};
    __half* outs[3] = {g_qh, g_kh, g_vh};
    const size_t inbase = ((size_t)n * LSEQ + tile * 256) * EMB + (size_t)h * HD;

#pragma unroll 1
    for (int w = 0; w < 3; w++) {
        __syncthreads();

#pragma unroll
        for (int u = 0; u < 8; u++) {
            int cl = tid + u * 256;
            int row = cl >> 3, c = cl & 7;
            const float4* src = reinterpret_cast<const float4*>(ins[w] + inbase + (size_t)row * EMB);
            float4 f0 = src[c * 2], f1 = src[c * 2 + 1];
            uint4 pk;
            pk.x = cvt_h2(f0.x, f0.y); pk.y = cvt_h2(f0.z, f0.w);
            pk.z = cvt_h2(f1.x, f1.y); pk.w = cvt_h2(f1.z, f1.w);
            *reinterpret_cast<uint4*>(sm + QKV_SMX + row * 128 + ((c ^ (row & 7)) << 4)) = pk;
        }
        __syncthreads();

        uint32_t af[2][4][4];
#pragma unroll
        for (int mi = 0; mi < 2; mi++) {
            const int mrow = wid * 32 + mi * 16 + 8 * (lm & 1) + lr;
#pragma unroll
            for (int ks = 0; ks < 4; ks++) {
                const uint32_t addr = smb + QKV_SMX + mrow * 128 +
                    ((((ks << 1) | (lm >> 1)) ^ (mrow & 7)) << 4);
                LDMX4(af[mi][ks][0], af[mi][ks][1], af[mi][ks][2], af[mi][ks][3], addr);
            }
        }

        float c[2][8][4];
#pragma unroll
        for (int mi = 0; mi < 2; mi++)
#pragma unroll
            for (int ni = 0; ni < 8; ni++)
#pragma unroll
                for (int j = 0; j < 4; j++) c[mi][ni][j] = 0.f;

#pragma unroll
        for (int ks = 0; ks < 4; ks++) {
#pragma unroll
            for (int np = 0; np < 4; np++) {
                const int wrow = np * 16 + 8 * (lm >> 1) + lr;
                const uint32_t addr = smb + w * 8192 + wrow * 128 +
                    ((((ks << 1) | (lm & 1)) ^ (wrow & 7)) << 4);
                uint32_t bf[4];
                LDMX4(bf[0], bf[1], bf[2], bf[3], addr);
#pragma unroll
                for (int mi = 0; mi < 2; mi++) {
                    mma16816h(c[mi][2*np],   af[mi][ks], bf[0], bf[1]);
                    mma16816h(c[mi][2*np+1], af[mi][ks], bf[2], bf[3]);
                }
            }
        }

        uint32_t* out32 = reinterpret_cast<uint32_t*>(outs[w]);
        const int l0 = tile * 256 + wid * 32;
#pragma unroll
        for (int mi = 0; mi < 2; mi++) {
            const int l1 = l0 + mi * 16 + g, l2 = l1 + 8;
            const size_t r1 = ((size_t)bh * LSEQ + l1) * 32;
            const size_t r2 = ((size_t)bh * LSEQ + l2) * 32;
#pragma unroll
            for (int nt = 0; nt < 8; nt++) {
                float v0 = c[mi][nt][0], v1 = c[mi][nt][1];
                float v2 = c[mi][nt][2], v3 = c[mi][nt][3];
                if (w == 0) { v0 *= QS; v1 *= QS; v2 *= QS; v3 *= QS; }
                if (w == 0) {
                    out32[r1 + 4 * nt + t] = cvt_h2(v0, v1);
                    out32[r2 + 4 * nt + t] = cvt_h2(v2, v3);
                } else {
                    out32[r1 + (((nt ^ (l1 & 7)) << 2) | t)] = cvt_h2(v0, v1);
                    out32[r2 + (((nt ^ (l2 & 7)) << 2) | t)] = cvt_h2(v2, v3);
                }
            }
        }
    }
}

// ---------------------------------------------------------------------------
// Kernel 2: flash attention fp16, 3-stage cp.async.bulk pipeline.
// ---------------------------------------------------------------------------
#define ABUF 8192
#define ASTG 16384
#define SM_ATT 49176    // 3 stages + 3 mbars at +49152

__global__ void __launch_bounds__(256, 2) attn_kernel()
{
    extern __shared__ char sm[];
    const uint32_t smb = smem_u32(sm);
    const uint32_t mb[3] = {smb + 49152, smb + 49160, smb + 49168};
    const int tid = threadIdx.x, wid = tid >> 5, lane = tid & 31;
    const int g = lane >> 2, t = lane & 3;
    const int bh = blockIdx.y;
    const int q0 = blockIdx.x * 128;
    const int warp_q = q0 + wid * 16;

    const int lm = lane >> 3, lr = lane & 7;
    const int kcb = lm & 1;
    const uint32_t krb = (uint32_t)((8 * (lm >> 1) + lr) * 128);
    const int vcb = lm >> 1;
    const uint32_t vrb = (uint32_t)(((lm & 1) * 8 + lr) * 128);

    if (tid == 0) { MBAR_INIT(mb[0], 1); MBAR_INIT(mb[1], 1); MBAR_INIT(mb[2], 1); }
    __syncthreads();

    uint32_t qh[4][4];
    {
        const uint32_t* bhp = reinterpret_cast<const uint32_t*>(g_qh) + ((size_t)bh * LSEQ + warp_q) * 32;
#pragma unroll
        for (int ks = 0; ks < 4; ks++) {
            qh[ks][0] = bhp[(size_t)g * 32 + 8*ks + t];
            qh[ks][1] = bhp[(size_t)(g+8) * 32 + 8*ks + t];
            qh[ks][2] = bhp[(size_t)g * 32 + 8*ks + t + 4];
            qh[ks][3] = bhp[(size_t)(g+8) * 32 + 8*ks + t + 4];
        }
    }

    auto issue_stage = [&](int kt, int s) {
        const uint32_t sb = smb + s * ASTG;
        const size_t go = ((size_t)bh * LSEQ + kt * 64) * HD;
        MBAR_EXPECT_TX(mb[s], 2 * ABUF);
        CP_BULK(sb,            (const char*)g_kh + go * 2, ABUF, mb[s]);
        CP_BULK(sb + ABUF,     (const char*)g_vh + go * 2, ABUF, mb[s]);
    };

    float o[8][4];
#pragma unroll
    for (int i = 0; i < 8; i++)
#pragma unroll
        for (int j = 0; j < 4; j++) o[i][j] = 0.f;
    float lsacc[4] = {0.f, 0.f, 0.f, 0.f};

    if (tid == 0) { issue_stage(0, 0); issue_stage(1, 1); }

    for (int kt = 0; kt < 32; kt++) {
        const int s = kt % 3;
        if (kt < 30 && tid == 0) issue_stage(kt + 2, (kt + 2) % 3);
        MBAR_WAIT(mb[s], (kt / 3) & 1);

        const uint32_t KHb = smb + s * ASTG;
        const uint32_t VHb = KHb + ABUF;

#pragma unroll
        for (int half = 0; half < 2; half++) {
            const uint32_t hoff = half * 4096;

            float sc[4][4];
#pragma unroll
            for (int nt = 0; nt < 4; nt++)
#pragma unroll
                for (int j = 0; j < 4; j++) sc[nt][j] = 0.f;

#pragma unroll
            for (int ks = 0; ks < 4; ks++) {
                const uint32_t csw = (uint32_t)((((ks << 1) | kcb) ^ lr) << 4);
                uint32_t kf[8];
                LDMX4(kf[0], kf[1], kf[2], kf[3], KHb + hoff + krb + csw);
                LDMX4(kf[4], kf[5], kf[6], kf[7], KHb + hoff + 2048 + krb + csw);
#pragma unroll
                for (int nt = 0; nt < 4; nt++)
                    mma16816h(sc[nt], qh[ks], kf[2*nt], kf[2*nt+1]);
            }

            uint32_t ph[2][4];
#pragma unroll
            for (int nt = 0; nt < 4; nt++) {
                const int kc = nt >> 1, su = (nt & 1) * 2;
                ph[kc][su + 0] = ex2_h2(cvt_h2(sc[nt][0], sc[nt][1]));
                ph[kc][su + 1] = ex2_h2(cvt_h2(sc[nt][2], sc[nt][3]));
            }

#pragma unroll
            for (int kc = 0; kc < 2; kc++) {
                const uint32_t kb = hoff + kc * 2048;
#pragma unroll
                for (int db = 0; db < 4; db++) {
                    const uint32_t csw = (uint32_t)((((db << 1) | vcb) ^ lr) << 4);
                    uint32_t vhf[4];
                    LDMX4T(vhf[0], vhf[1], vhf[2], vhf[3], VHb + kb + vrb + csw);
                    mma16816h(o[2*db],   ph[kc], vhf[0], vhf[1]);
                    mma16816h(o[2*db+1], ph[kc], vhf[2], vhf[3]);
                }
                mma16816h(lsacc, ph[kc], HONES, HONES);
            }
        }
        __syncthreads();
    }

    const float inv0 = 1.f / lsacc[0], inv1 = 1.f / lsacc[2];

    const int n = bh >> 4, h = bh & 15;
    const int gt1 = n * LSEQ + warp_q + g;
    const int gt2 = gt1 + 8;
    const int mb1 = gt1 >> 7, mr1 = gt1 & 127;
    const int mb2 = gt2 >> 7, mr2 = gt2 & 127;
#pragma unroll
    for (int nd = 0; nd < 8; nd++) {
        const int dcol = 8 * nd + 2 * t;
        const int kb = h * 2 + (dcol >> 5);
        const int c = dcol & 31;
        const size_t i1 = (((size_t)(mb1 * 32 + kb) * 128 + mr1) * 40 + c) >> 1;
        const size_t i2 = (((size_t)(mb2 * 32 + kb) * 128 + mr2) * 40 + c) >> 1;
        reinterpret_cast<uint32_t*>(g_ao_t)[i1] = cvt_h2(o[nd][0] * inv0, o[nd][1] * inv0);
        reinterpret_cast<uint32_t*>(g_ao_t)[i2] = cvt_h2(o[nd][2] * inv1, o[nd][3] * inv1);
    }
}

// ---------------------------------------------------------------------------
// Kernel 3: output projection, fp16 single-pass, 3-stage pipeline.
// ---------------------------------------------------------------------------
#define OSTRB 80
#define OBUF  10240
#define OSTG  20480
#define SM_GEMM 61464   // 3 stages + 3 mbars at +61440

__global__ void __launch_bounds__(256, 2) out_proj_kernel(
    const float* __restrict__ bias, float* __restrict__ C)
{
    extern __shared__ char sm[];
    const uint32_t smb = smem_u32(sm);
    const uint32_t mb[3] = {smb + 61440, smb + 61448, smb + 61456};
    const int tid = threadIdx.x, wid = tid >> 5, lane = tid & 31;
    const int g = lane >> 2, t = lane & 3;
    const int lm = lane >> 3, lr = lane & 7;
    const int m0 = blockIdx.y * 128;
    const int n0 = blockIdx.x * 128;
    const int wm = (wid & 3) * 32;
    const int wn = (wid >> 2) * 64;

    const uint32_t a_lmo = (uint32_t)(((lm & 1) * 8 + lr) * OSTRB + (lm >> 1) * 16);
    const uint32_t b_lmo = (uint32_t)(((lm >> 1) * 8 + lr) * OSTRB + (lm & 1) * 16);

    if (tid == 0) { MBAR_INIT(mb[0], 1); MBAR_INIT(mb[1], 1); MBAR_INIT(mb[2], 1); }
    __syncthreads();

    auto issue_stage = [&](int kt, int s) {
        const uint32_t sb = smb + s * OSTG;
        const size_t ao = (size_t)(blockIdx.y * 32 + kt) * (128 * 40);
        const size_t wo = (size_t)(blockIdx.x * 32 + kt) * (128 * 40);
        MBAR_EXPECT_TX(mb[s], 2 * OBUF);
        CP_BULK(sb,           (const char*)g_ao_t + ao * 2, OBUF, mb[s]);
        CP_BULK(sb + OBUF,    (const char*)g_wo_t + wo * 2, OBUF, mb[s]);
    };

    float acc[2][8][4];
#pragma unroll
    for (int i = 0; i < 2; i++)
#pragma unroll
        for (int j = 0; j < 8; j++)
#pragma unroll
            for (int k = 0; k < 4; k++) acc[i][j][k] = 0.f;

    if (tid == 0) { issue_stage(0, 0); issue_stage(1, 1); }

    for (int kt = 0; kt < 32; kt++) {
        const int s = kt % 3;
        if (kt < 30 && tid == 0) issue_stage(kt + 2, (kt + 2) % 3);
        MBAR_WAIT(mb[s], (kt / 3) & 1);

        const uint32_t Ao = smb + s * OSTG;
        const uint32_t Bo = Ao + OBUF;

#pragma unroll
        for (int ks = 0; ks < 2; ks++) {
            uint32_t ah[2][4];
#pragma unroll
            for (int mi = 0; mi < 2; mi++)
                LDMX4(ah[mi][0], ah[mi][1], ah[mi][2], ah[mi][3],
                      Ao + (wm + mi * 16) * OSTRB + ks * 32 + a_lmo);
#pragma unroll
            for (int ni = 0; ni < 8; ni += 2) {
                uint32_t bf[4];
                LDMX4(bf[0], bf[1], bf[2], bf[3],
                      Bo + (wn + ni * 8) * OSTRB + ks * 32 + b_lmo);
#pragma unroll
                for (int mi = 0; mi < 2; mi++) {
                    mma16816h(acc[mi][ni],     ah[mi], bf[0], bf[1]);
                    mma16816h(acc[mi][ni + 1], ah[mi], bf[2], bf[3]);
                }
            }
        }
        __syncthreads();
    }

#pragma unroll
    for (int mi = 0; mi < 2; mi++) {
        const int r1 = m0 + wm + mi * 16 + g;
        const int r2 = r1 + 8;
#pragma unroll
        for (int ni = 0; ni < 8; ni++) {
            const int col = n0 + wn + ni * 8 + 2 * t;
            float2 bv = *reinterpret_cast<const float2*>(bias + col);
            *reinterpret_cast<float2*>(C + (size_t)r1 * EMB + col) =
                make_float2(acc[mi][ni][0] + bv.x, acc[mi][ni][1] + bv.y);
            *reinterpret_cast<float2*>(C + (size_t)r2 * EMB + col) =
                make_float2(acc[mi][ni][2] + bv.x, acc[mi][ni][3] + bv.y);
        }
    }
}

// ---------------------------------------------------------------------------
extern "C" void kernel_launch(void* const* d_in, const int* in_sizes, int n_in,
                              void* d_out, int out_size)
{
    const float* values  = (const float*)d_in[0];
    const float* keys    = (const float*)d_in[1];
    const float* queries = (const float*)d_in[2];
    const float* Wv      = (const float*)d_in[3];
    const float* Wk      = (const float*)d_in[4];
    const float* Wq      = (const float*)d_in[5];
    const float* Wo      = (const float*)d_in[6];
    const float* bo      = (const float*)d_in[7];
    float* out = (float*)d_out;

    static bool attr_set = false;
    if (!attr_set) {
        cudaFuncSetAttribute(qkv_mma_kernel,
                             cudaFuncAttributeMaxDynamicSharedMemorySize, QKV_SMT);
        cudaFuncSetAttribute(attn_kernel,
                             cudaFuncAttributeMaxDynamicSharedMemorySize, SM_ATT);
        cudaFuncSetAttribute(out_proj_kernel,
                             cudaFuncAttributeMaxDynamicSharedMemorySize, SM_GEMM);
        attr_set = true;
    }

    dim3 g1(LSEQ / 256, BHN, 2);   // z=0: qkv, z=1: Wo tiling
    qkv_mma_kernel<<<g1, 256, QKV_SMT>>>(queries, keys, values, Wq, Wk, Wv, Wo);

    dim3 g2(LSEQ / 128, BHN);
    attn_kernel<<<g2, 256, SM_ATT>>>();

    dim3 g3(EMB / 128, (NB * LSEQ) / 128);
    out_proj_kernel<<<g3, 256, SM_GEMM>>>(bo, out);
}

// round 15
// speedup vs baseline: 1.2221x; 1.2221x over previous
#include <cuda_runtime.h>
#include <cuda_fp16.h>
#include <math.h>
#include <stdint.h>

#define NB   4
#define LSEQ 2048
#define EMB  1024
#define NH   16
#define HD   64
#define BHN  (NB*NH)
// Q pre-scale: (1/sqrt(EMB)) * log2(e)  -> scores come out in log2 domain
#define QS   (0.04508422f)
#define HONES 0x3C003C00u     // fp16x2 {1.0, 1.0}

// ---------------- scratch ----------------
__device__ __half g_qh[BHN*LSEQ*HD];          // fp16 [bh][l][d] (pre-scaled, linear)
__device__ __half g_kh[BHN*LSEQ*HD];          // fp16 [bh][l][d] XOR-swizzled chunks
__device__ __half g_vh[BHN*LSEQ*HD];          // fp16, swizzled
// attention out, TILED fp16: [mb 64][kb 32][128 rows][40 half (32 data + 8 pad)]
__device__ __half g_ao_t[64*32*128*40];
// Wo, TILED fp16: [nb 8][kb 32][128][40]
__device__ __half g_wo_t[8*32*128*40];

__device__ __forceinline__ uint32_t cvt_h2(float a, float b) {   // a -> low half
    uint32_t r; asm("cvt.rn.f16x2.f32 %0, %1, %2;" : "=r"(r) : "f"(b), "f"(a)); return r;
}
__device__ __forceinline__ uint32_t ex2_h2(uint32_t s) {
    uint32_t r; asm("ex2.approx.f16x2 %0, %1;" : "=r"(r) : "r"(s)); return r;
}
__device__ __forceinline__ uint32_t smem_u32(const void* p) {
    uint32_t a;
    asm("{ .reg .u64 t; cvta.to.shared.u64 t, %1; cvt.u32.u64 %0, t; }" : "=r"(a) : "l"(p));
    return a;
}
__device__ __forceinline__ void mma16816h(float* c, const uint32_t* a,
                                          uint32_t b0, uint32_t b1) {
    asm volatile("mma.sync.aligned.m16n8k16.row.col.f32.f16.f16.f32 "
        "{%0,%1,%2,%3}, {%4,%5,%6,%7}, {%8,%9}, {%0,%1,%2,%3};"
        : "+f"(c[0]), "+f"(c[1]), "+f"(c[2]), "+f"(c[3])
        : "r"(a[0]), "r"(a[1]), "r"(a[2]), "r"(a[3]), "r"(b0), "r"(b1));
}
#define LDMX4(r0, r1, r2, r3, addr) \
    asm volatile("ldmatrix.sync.aligned.m8n8.x4.shared.b16 {%0,%1,%2,%3}, [%4];" \
        : "=r"(r0), "=r"(r1), "=r"(r2), "=r"(r3) : "r"(addr))
#define LDMX4T(r0, r1, r2, r3, addr) \
    asm volatile("ldmatrix.sync.aligned.m8n8.x4.trans.shared.b16 {%0,%1,%2,%3}, [%4];" \
        : "=r"(r0), "=r"(r1), "=r"(r2), "=r"(r3) : "r"(addr))

#define CP_BULK(dst, src, bytes, mbar) \
    asm volatile("cp.async.bulk.shared::cta.global.mbarrier::complete_tx::bytes [%0], [%1], %2, [%3];" \
        :: "r"(dst), "l"(src), "r"((uint32_t)(bytes)), "r"(mbar) : "memory")
#define MBAR_INIT(a, c) \
    asm volatile("mbarrier.init.shared.b64 [%0], %1;" :: "r"(a), "r"((uint32_t)(c)) : "memory")
#define MBAR_EXPECT_TX(a, tx) \
    asm volatile("mbarrier.arrive.expect_tx.shared.b64 _, [%0], %1;" :: "r"(a), "r"((uint32_t)(tx)) : "memory")
#define MBAR_WAIT(mbar, par) do {                                              \
    uint32_t _m = (mbar), _p = (par), _d;                                      \
    asm volatile("{\n\t.reg .pred p;\n\t"                                      \
        "mbarrier.try_wait.parity.acquire.cta.shared::cta.b64 p, [%1], %2;\n\t"\
        "selp.b32 %0, 1, 0, p;\n\t}" : "=r"(_d) : "r"(_m), "r"(_p) : "memory");\
    if (!_d) {                                                                 \
        asm volatile("{\n\t.reg .pred P1;\n\t"                                 \
            "W_%=:\n\t"                                                        \
            "mbarrier.try_wait.parity.acquire.cta.shared::cta.b64 P1, [%0], %1, 0x989680;\n\t" \
            "@P1 bra.uni D_%=;\n\t"                                            \
            "bra.uni W_%=;\n\t"                                                \
            "D_%=:\n\t}" :: "r"(_m), "r"(_p) : "memory");                      \
    }                                                                          \
} while (0)

// ---------------------------------------------------------------------------
// Kernel 0: Wo (fp32) -> fp16 TILED [nb][kb][128][40]
// ---------------------------------------------------------------------------
__global__ void __launch_bounds__(256) wo_split_kernel(const float* __restrict__ Wo)
{
    const int i4 = (blockIdx.x * 256 + threadIdx.x) * 4;
    const int e = i4 >> 10, k = i4 & 1023;
    float4 w = *reinterpret_cast<const float4*>(Wo + i4);
    const int nb = e >> 7, er = e & 127, kb = k >> 5, c = k & 31;
    const size_t base = ((size_t)(nb * 32 + kb) * 128 + er) * 40 + c;
    uint32_t* oh = reinterpret_cast<uint32_t*>(g_wo_t + base);
    oh[0] = cvt_h2(w.x, w.y); oh[1] = cvt_h2(w.z, w.w);
}

// ---------------------------------------------------------------------------
// Kernel 1: QKV projection, one input per CTA (grid.z selects q/k/v).
// smem: W fp16 swizzled (8KB) + X fp16 swizzled (32KB). 2 CTAs/SM.
// ---------------------------------------------------------------------------
#define QKV_SM 40960    // 8192 (W) + 32768 (X: 256 rows x 128B)

__global__ void __launch_bounds__(256, 2) qkv_mma_kernel(
    const float* __restrict__ q_in, const float* __restrict__ k_in,
    const float* __restrict__ v_in,
    const float* __restrict__ Wq, const float* __restrict__ Wk,
    const float* __restrict__ Wv)
{
    extern __shared__ char sm[];
    const uint32_t smb = smem_u32(sm);
    const int tid = threadIdx.x, wid = tid >> 5, lane = tid & 31;
    const int g = lane >> 2, t = lane & 3;
    const int lm = lane >> 3, lr = lane & 7;
    const int z = blockIdx.z;
    const int bh = blockIdx.y;
    const int tile = blockIdx.x;
    const int n = bh >> 4, h = bh & 15;

    const float* xin = (z == 0) ? q_in : (z == 1) ? k_in : v_in;
    const float* W   = (z == 0) ? Wq   : (z == 1) ? Wk   : Wv;
    __half* outp     = (z == 0) ? g_qh : (z == 1) ? g_kh : g_vh;

    // ---- weight fp32 -> fp16 swizzled smem (512 chunks, 2/thread) ----
#pragma unroll
    for (int u = 0; u < 2; u++) {
        int cl = tid + u * 256;
        int row = cl >> 3, c = cl & 7;
        float4 f0 = reinterpret_cast<const float4*>(W)[row * 16 + c * 2];
        float4 f1 = reinterpret_cast<const float4*>(W)[row * 16 + c * 2 + 1];
        uint4 pk;
        pk.x = cvt_h2(f0.x, f0.y); pk.y = cvt_h2(f0.z, f0.w);
        pk.z = cvt_h2(f1.x, f1.y); pk.w = cvt_h2(f1.z, f1.w);
        *reinterpret_cast<uint4*>(sm + row * 128 + ((c ^ (row & 7)) << 4)) = pk;
    }

    // ---- X tile fp32 -> fp16 swizzled smem (2048 chunks, 8/thread) ----
    const size_t inbase = ((size_t)n * LSEQ + tile * 256) * EMB + (size_t)h * HD;
#pragma unroll
    for (int u = 0; u < 8; u++) {
        int cl = tid + u * 256;
        int row = cl >> 3, c = cl & 7;
        const float4* src = reinterpret_cast<const float4*>(xin + inbase + (size_t)row * EMB);
        float4 f0 = src[c * 2], f1 = src[c * 2 + 1];
        uint4 pk;
        pk.x = cvt_h2(f0.x, f0.y); pk.y = cvt_h2(f0.z, f0.w);
        pk.z = cvt_h2(f1.x, f1.y); pk.w = cvt_h2(f1.z, f1.w);
        *reinterpret_cast<uint4*>(sm + 8192 + row * 128 + ((c ^ (row & 7)) << 4)) = pk;
    }
    __syncthreads();

    // ---- GEMM: A fragments loaded per k-step (low reg pressure) ----
    float c[2][8][4];
#pragma unroll
    for (int mi = 0; mi < 2; mi++)
#pragma unroll
        for (int ni = 0; ni < 8; ni++)
#pragma unroll
            for (int j = 0; j < 4; j++) c[mi][ni][j] = 0.f;

#pragma unroll
    for (int ks = 0; ks < 4; ks++) {
        uint32_t af[2][4];
#pragma unroll
        for (int mi = 0; mi < 2; mi++) {
            const int mrow = wid * 32 + mi * 16 + 8 * (lm & 1) + lr;
            const uint32_t addr = smb + 8192 + mrow * 128 +
                ((((ks << 1) | (lm >> 1)) ^ (mrow & 7)) << 4);
            LDMX4(af[mi][0], af[mi][1], af[mi][2], af[mi][3], addr);
        }
#pragma unroll
        for (int np = 0; np < 4; np++) {
            const int wrow = np * 16 + 8 * (lm >> 1) + lr;
            const uint32_t addr = smb + wrow * 128 +
                ((((ks << 1) | (lm & 1)) ^ (wrow & 7)) << 4);
            uint32_t bf[4];
            LDMX4(bf[0], bf[1], bf[2], bf[3], addr);
#pragma unroll
            for (int mi = 0; mi < 2; mi++) {
                mma16816h(c[mi][2*np],   af[mi], bf[0], bf[1]);
                mma16816h(c[mi][2*np+1], af[mi], bf[2], bf[3]);
            }
        }
    }

    // ---- epilogue: Q linear (scaled), K/V swizzled ----
    uint32_t* out32 = reinterpret_cast<uint32_t*>(outp);
    const int l0 = tile * 256 + wid * 32;
#pragma unroll
    for (int mi = 0; mi < 2; mi++) {
        const int l1 = l0 + mi * 16 + g, l2 = l1 + 8;
        const size_t r1 = ((size_t)bh * LSEQ + l1) * 32;
        const size_t r2 = ((size_t)bh * LSEQ + l2) * 32;
#pragma unroll
        for (int nt = 0; nt < 8; nt++) {
            float v0 = c[mi][nt][0], v1 = c[mi][nt][1];
            float v2 = c[mi][nt][2], v3 = c[mi][nt][3];
            if (z == 0) {
                out32[r1 + 4 * nt + t] = cvt_h2(v0 * QS, v1 * QS);
                out32[r2 + 4 * nt + t] = cvt_h2(v2 * QS, v3 * QS);
            } else {
                out32[r1 + (((nt ^ (l1 & 7)) << 2) | t)] = cvt_h2(v0, v1);
                out32[r2 + (((nt ^ (l2 & 7)) << 2) | t)] = cvt_h2(v2, v3);
            }
        }
    }
}

// ---------------------------------------------------------------------------
// Kernel 2: flash attention fp16, 3-stage cp.async.bulk pipeline.
// ---------------------------------------------------------------------------
#define ABUF 8192
#define ASTG 16384
#define SM_ATT 49176    // 3 stages + 3 mbars at +49152

__global__ void __launch_bounds__(256, 2) attn_kernel()
{
    extern __shared__ char sm[];
    const uint32_t smb = smem_u32(sm);
    const uint32_t mb[3] = {smb + 49152, smb + 49160, smb + 49168};
    const int tid = threadIdx.x, wid = tid >> 5, lane = tid & 31;
    const int g = lane >> 2, t = lane & 3;
    const int bh = blockIdx.y;
    const int q0 = blockIdx.x * 128;
    const int warp_q = q0 + wid * 16;

    const int lm = lane >> 3, lr = lane & 7;
    const int kcb = lm & 1;
    const uint32_t krb = (uint32_t)((8 * (lm >> 1) + lr) * 128);
    const int vcb = lm >> 1;
    const uint32_t vrb = (uint32_t)(((lm & 1) * 8 + lr) * 128);

    if (tid == 0) { MBAR_INIT(mb[0], 1); MBAR_INIT(mb[1], 1); MBAR_INIT(mb[2], 1); }
    __syncthreads();

    uint32_t qh[4][4];
    {
        const uint32_t* bhp = reinterpret_cast<const uint32_t*>(g_qh) + ((size_t)bh * LSEQ + warp_q) * 32;
#pragma unroll
        for (int ks = 0; ks < 4; ks++) {
            qh[ks][0] = bhp[(size_t)g * 32 + 8*ks + t];
            qh[ks][1] = bhp[(size_t)(g+8) * 32 + 8*ks + t];
            qh[ks][2] = bhp[(size_t)g * 32 + 8*ks + t + 4];
            qh[ks][3] = bhp[(size_t)(g+8) * 32 + 8*ks + t + 4];
        }
    }

    auto issue_stage = [&](int kt, int s) {
        const uint32_t sb = smb + s * ASTG;
        const size_t go = ((size_t)bh * LSEQ + kt * 64) * HD;
        MBAR_EXPECT_TX(mb[s], 2 * ABUF);
        CP_BULK(sb,            (const char*)g_kh + go * 2, ABUF, mb[s]);
        CP_BULK(sb + ABUF,     (const char*)g_vh + go * 2, ABUF, mb[s]);
    };

    float o[8][4];
#pragma unroll
    for (int i = 0; i < 8; i++)
#pragma unroll
        for (int j = 0; j < 4; j++) o[i][j] = 0.f;
    float lsacc[4] = {0.f, 0.f, 0.f, 0.f};

    if (tid == 0) { issue_stage(0, 0); issue_stage(1, 1); }

    for (int kt = 0; kt < 32; kt++) {
        const int s = kt % 3;
        if (kt < 30 && tid == 0) issue_stage(kt + 2, (kt + 2) % 3);
        MBAR_WAIT(mb[s], (kt / 3) & 1);

        const uint32_t KHb = smb + s * ASTG;
        const uint32_t VHb = KHb + ABUF;

#pragma unroll
        for (int half = 0; half < 2; half++) {
            const uint32_t hoff = half * 4096;

            float sc[4][4];
#pragma unroll
            for (int nt = 0; nt < 4; nt++)
#pragma unroll
                for (int j = 0; j < 4; j++) sc[nt][j] = 0.f;

#pragma unroll
            for (int ks = 0; ks < 4; ks++) {
                const uint32_t csw = (uint32_t)((((ks << 1) | kcb) ^ lr) << 4);
                uint32_t kf[8];
                LDMX4(kf[0], kf[1], kf[2], kf[3], KHb + hoff + krb + csw);
                LDMX4(kf[4], kf[5], kf[6], kf[7], KHb + hoff + 2048 + krb + csw);
#pragma unroll
                for (int nt = 0; nt < 4; nt++)
                    mma16816h(sc[nt], qh[ks], kf[2*nt], kf[2*nt+1]);
            }

            uint32_t ph[2][4];
#pragma unroll
            for (int nt = 0; nt < 4; nt++) {
                const int kc = nt >> 1, su = (nt & 1) * 2;
                ph[kc][su + 0] = ex2_h2(cvt_h2(sc[nt][0], sc[nt][1]));
                ph[kc][su + 1] = ex2_h2(cvt_h2(sc[nt][2], sc[nt][3]));
            }

#pragma unroll
            for (int kc = 0; kc < 2; kc++) {
                const uint32_t kb = hoff + kc * 2048;
#pragma unroll
                for (int db = 0; db < 4; db++) {
                    const uint32_t csw = (uint32_t)((((db << 1) | vcb) ^ lr) << 4);
                    uint32_t vhf[4];
                    LDMX4T(vhf[0], vhf[1], vhf[2], vhf[3], VHb + kb + vrb + csw);
                    mma16816h(o[2*db],   ph[kc], vhf[0], vhf[1]);
                    mma16816h(o[2*db+1], ph[kc], vhf[2], vhf[3]);
                }
                mma16816h(lsacc, ph[kc], HONES, HONES);
            }
        }
        __syncthreads();
    }

    const float inv0 = 1.f / lsacc[0], inv1 = 1.f / lsacc[2];

    const int n = bh >> 4, h = bh & 15;
    const int gt1 = n * LSEQ + warp_q + g;
    const int gt2 = gt1 + 8;
    const int mb1 = gt1 >> 7, mr1 = gt1 & 127;
    const int mb2 = gt2 >> 7, mr2 = gt2 & 127;
#pragma unroll
    for (int nd = 0; nd < 8; nd++) {
        const int dcol = 8 * nd + 2 * t;
        const int kb = h * 2 + (dcol >> 5);
        const int c = dcol & 31;
        const size_t i1 = (((size_t)(mb1 * 32 + kb) * 128 + mr1) * 40 + c) >> 1;
        const size_t i2 = (((size_t)(mb2 * 32 + kb) * 128 + mr2) * 40 + c) >> 1;
        reinterpret_cast<uint32_t*>(g_ao_t)[i1] = cvt_h2(o[nd][0] * inv0, o[nd][1] * inv0);
        reinterpret_cast<uint32_t*>(g_ao_t)[i2] = cvt_h2(o[nd][2] * inv1, o[nd][3] * inv1);
    }
}

// ---------------------------------------------------------------------------
// Kernel 3: output projection, fp16 single-pass, 3-stage pipeline.
// ---------------------------------------------------------------------------
#define OSTRB 80
#define OBUF  10240
#define OSTG  20480
#define SM_GEMM 61464   // 3 stages + 3 mbars at +61440

__global__ void __launch_bounds__(256, 2) out_proj_kernel(
    const float* __restrict__ bias, float* __restrict__ C)
{
    extern __shared__ char sm[];
    const uint32_t smb = smem_u32(sm);
    const uint32_t mb[3] = {smb + 61440, smb + 61448, smb + 61456};
    const int tid = threadIdx.x, wid = tid >> 5, lane = tid & 31;
    const int g = lane >> 2, t = lane & 3;
    const int lm = lane >> 3, lr = lane & 7;
    const int m0 = blockIdx.y * 128;
    const int n0 = blockIdx.x * 128;
    const int wm = (wid & 3) * 32;
    const int wn = (wid >> 2) * 64;

    const uint32_t a_lmo = (uint32_t)(((lm & 1) * 8 + lr) * OSTRB + (lm >> 1) * 16);
    const uint32_t b_lmo = (uint32_t)(((lm >> 1) * 8 + lr) * OSTRB + (lm & 1) * 16);

    if (tid == 0) { MBAR_INIT(mb[0], 1); MBAR_INIT(mb[1], 1); MBAR_INIT(mb[2], 1); }
    __syncthreads();

    auto issue_stage = [&](int kt, int s) {
        const uint32_t sb = smb + s * OSTG;
        const size_t ao = (size_t)(blockIdx.y * 32 + kt) * (128 * 40);
        const size_t wo = (size_t)(blockIdx.x * 32 + kt) * (128 * 40);
        MBAR_EXPECT_TX(mb[s], 2 * OBUF);
        CP_BULK(sb,           (const char*)g_ao_t + ao * 2, OBUF, mb[s]);
        CP_BULK(sb + OBUF,    (const char*)g_wo_t + wo * 2, OBUF, mb[s]);
    };

    float acc[2][8][4];
#pragma unroll
    for (int i = 0; i < 2; i++)
#pragma unroll
        for (int j = 0; j < 8; j++)
#pragma unroll
            for (int k = 0; k < 4; k++) acc[i][j][k] = 0.f;

    if (tid == 0) { issue_stage(0, 0); issue_stage(1, 1); }

    for (int kt = 0; kt < 32; kt++) {
        const int s = kt % 3;
        if (kt < 30 && tid == 0) issue_stage(kt + 2, (kt + 2) % 3);
        MBAR_WAIT(mb[s], (kt / 3) & 1);

        const uint32_t Ao = smb + s * OSTG;
        const uint32_t Bo = Ao + OBUF;

#pragma unroll
        for (int ks = 0; ks < 2; ks++) {
            uint32_t ah[2][4];
#pragma unroll
            for (int mi = 0; mi < 2; mi++)
                LDMX4(ah[mi][0], ah[mi][1], ah[mi][2], ah[mi][3],
                      Ao + (wm + mi * 16) * OSTRB + ks * 32 + a_lmo);
#pragma unroll
            for (int ni = 0; ni < 8; ni += 2) {
                uint32_t bf[4];
                LDMX4(bf[0], bf[1], bf[2], bf[3],
                      Bo + (wn + ni * 8) * OSTRB + ks * 32 + b_lmo);
#pragma unroll
                for (int mi = 0; mi < 2; mi++) {
                    mma16816h(acc[mi][ni],     ah[mi], bf[0], bf[1]);
                    mma16816h(acc[mi][ni + 1], ah[mi], bf[2], bf[3]);
                }
            }
        }
        __syncthreads();
    }

#pragma unroll
    for (int mi = 0; mi < 2; mi++) {
        const int r1 = m0 + wm + mi * 16 + g;
        const int r2 = r1 + 8;
#pragma unroll
        for (int ni = 0; ni < 8; ni++) {
            const int col = n0 + wn + ni * 8 + 2 * t;
            float2 bv = *reinterpret_cast<const float2*>(bias + col);
            *reinterpret_cast<float2*>(C + (size_t)r1 * EMB + col) =
                make_float2(acc[mi][ni][0] + bv.x, acc[mi][ni][1] + bv.y);
            *reinterpret_cast<float2*>(C + (size_t)r2 * EMB + col) =
                make_float2(acc[mi][ni][2] + bv.x, acc[mi][ni][3] + bv.y);
        }
    }
}

// ---------------------------------------------------------------------------
extern "C" void kernel_launch(void* const* d_in, const int* in_sizes, int n_in,
                              void* d_out, int out_size)
{
    const float* values  = (const float*)d_in[0];
    const float* keys    = (const float*)d_in[1];
    const float* queries = (const float*)d_in[2];
    const float* Wv      = (const float*)d_in[3];
    const float* Wk      = (const float*)d_in[4];
    const float* Wq      = (const float*)d_in[5];
    const float* Wo      = (const float*)d_in[6];
    const float* bo      = (const float*)d_in[7];
    float* out = (float*)d_out;

    static bool attr_set = false;
    if (!attr_set) {
        cudaFuncSetAttribute(qkv_mma_kernel,
                             cudaFuncAttributeMaxDynamicSharedMemorySize, QKV_SM);
        cudaFuncSetAttribute(attn_kernel,
                             cudaFuncAttributeMaxDynamicSharedMemorySize, SM_ATT);
        cudaFuncSetAttribute(out_proj_kernel,
                             cudaFuncAttributeMaxDynamicSharedMemorySize, SM_GEMM);
        attr_set = true;
    }

    wo_split_kernel<<<EMB * EMB / 1024, 256>>>(Wo);

    dim3 g1(LSEQ / 256, BHN, 3);   // z: 0=q, 1=k, 2=v
    qkv_mma_kernel<<<g1, 256, QKV_SM>>>(queries, keys, values, Wq, Wk, Wv);

    dim3 g2(LSEQ / 128, BHN);
    attn_kernel<<<g2, 256, SM_ATT>>>();

    dim3 g3(EMB / 128, (NB * LSEQ) / 128);
    out_proj_kernel<<<g3, 256, SM_GEMM>>>(bo, out);
}

// round 16
// speedup vs baseline: 1.2943x; 1.0591x over previous
#include <cuda_runtime.h>
#include <cuda_fp16.h>
#include <math.h>
#include <stdint.h>

#define NB   4
#define LSEQ 2048
#define EMB  1024
#define NH   16
#define HD   64
#define BHN  (NB*NH)
// Q pre-scale: (1/sqrt(EMB)) * log2(e)  -> scores come out in log2 domain
#define QS   (0.04508422f)
#define HONES 0x3C003C00u     // fp16x2 {1.0, 1.0}

// ---------------- scratch ----------------
__device__ __half g_qh[BHN*LSEQ*HD];          // fp16 [bh][l][d] (pre-scaled, linear)
__device__ __half g_kh[BHN*LSEQ*HD];          // fp16 [bh][l][d] XOR-swizzled chunks
__device__ __half g_vh[BHN*LSEQ*HD];          // fp16, swizzled
// attention out, TILED fp16: [mb 64][kb 32][128 rows][40 half (32 data + 8 pad)]
__device__ __half g_ao_t[64*32*128*40];
// Wo, TILED fp16: [nb 8][kb 32][128][40]
__device__ __half g_wo_t[8*32*128*40];

__device__ __forceinline__ uint32_t cvt_h2(float a, float b) {   // a -> low half
    uint32_t r; asm("cvt.rn.f16x2.f32 %0, %1, %2;" : "=r"(r) : "f"(b), "f"(a)); return r;
}
__device__ __forceinline__ uint32_t ex2_h2(uint32_t s) {
    uint32_t r; asm("ex2.approx.f16x2 %0, %1;" : "=r"(r) : "r"(s)); return r;
}
__device__ __forceinline__ uint32_t smem_u32(const void* p) {
    uint32_t a;
    asm("{ .reg .u64 t; cvta.to.shared.u64 t, %1; cvt.u32.u64 %0, t; }" : "=r"(a) : "l"(p));
    return a;
}
__device__ __forceinline__ void mma16816h(float* c, const uint32_t* a,
                                          uint32_t b0, uint32_t b1) {
    asm volatile("mma.sync.aligned.m16n8k16.row.col.f32.f16.f16.f32 "
        "{%0,%1,%2,%3}, {%4,%5,%6,%7}, {%8,%9}, {%0,%1,%2,%3};"
        : "+f"(c[0]), "+f"(c[1]), "+f"(c[2]), "+f"(c[3])
        : "r"(a[0]), "r"(a[1]), "r"(a[2]), "r"(a[3]), "r"(b0), "r"(b1));
}
#define LDMX4(r0, r1, r2, r3, addr) \
    asm volatile("ldmatrix.sync.aligned.m8n8.x4.shared.b16 {%0,%1,%2,%3}, [%4];" \
        : "=r"(r0), "=r"(r1), "=r"(r2), "=r"(r3) : "r"(addr))
#define LDMX4T(r0, r1, r2, r3, addr) \
    asm volatile("ldmatrix.sync.aligned.m8n8.x4.trans.shared.b16 {%0,%1,%2,%3}, [%4];" \
        : "=r"(r0), "=r"(r1), "=r"(r2), "=r"(r3) : "r"(addr))

#define CP_BULK(dst, src, bytes, mbar) \
    asm volatile("cp.async.bulk.shared::cta.global.mbarrier::complete_tx::bytes [%0], [%1], %2, [%3];" \
        :: "r"(dst), "l"(src), "r"((uint32_t)(bytes)), "r"(mbar) : "memory")
#define MBAR_INIT(a, c) \
    asm volatile("mbarrier.init.shared.b64 [%0], %1;" :: "r"(a), "r"((uint32_t)(c)) : "memory")
#define MBAR_EXPECT_TX(a, tx) \
    asm volatile("mbarrier.arrive.expect_tx.shared.b64 _, [%0], %1;" :: "r"(a), "r"((uint32_t)(tx)) : "memory")
#define MBAR_WAIT(mbar, par) do {                                              \
    uint32_t _m = (mbar), _p = (par), _d;                                      \
    asm volatile("{\n\t.reg .pred p;\n\t"                                      \
        "mbarrier.try_wait.parity.acquire.cta.shared::cta.b64 p, [%1], %2;\n\t"\
        "selp.b32 %0, 1, 0, p;\n\t}" : "=r"(_d) : "r"(_m), "r"(_p) : "memory");\
    if (!_d) {                                                                 \
        asm volatile("{\n\t.reg .pred P1;\n\t"                                 \
            "W_%=:\n\t"                                                        \
            "mbarrier.try_wait.parity.acquire.cta.shared::cta.b64 P1, [%0], %1, 0x989680;\n\t" \
            "@P1 bra.uni D_%=;\n\t"                                            \
            "bra.uni W_%=;\n\t"                                                \
            "D_%=:\n\t}" :: "r"(_m), "r"(_p) : "memory");                      \
    }                                                                          \
} while (0)

// ---------------------------------------------------------------------------
// Kernel 1: QKV projection (z=0..2) + Wo tiling (z=3), one launch.
// smem: W fp16 swizzled (8KB) + X fp16 swizzled (32KB). 2 CTAs/SM.
// ---------------------------------------------------------------------------
#define QKV_SM 40960    // 8192 (W) + 32768 (X: 256 rows x 128B)

__global__ void __launch_bounds__(256, 2) qkv_mma_kernel(
    const float* __restrict__ q_in, const float* __restrict__ k_in,
    const float* __restrict__ v_in,
    const float* __restrict__ Wq, const float* __restrict__ Wk,
    const float* __restrict__ Wv, const float* __restrict__ Wo)
{
    const int tid = threadIdx.x;
    const int z = blockIdx.z;

    // ---- z=3: Wo fp32 -> fp16 TILED [nb][kb][128][40] ----
    if (z == 3) {
        const int bid = blockIdx.y * 8 + blockIdx.x;   // 0..511
#pragma unroll
        for (int u = 0; u < 2; u++) {
            const int i4 = (bid * 512 + u * 256 + tid) * 4;
            const int e = i4 >> 10, k = i4 & 1023;
            float4 w = *reinterpret_cast<const float4*>(Wo + i4);
            const int nb = e >> 7, er = e & 127, kb = k >> 5, c = k & 31;
            const size_t base = ((size_t)(nb * 32 + kb) * 128 + er) * 40 + c;
            uint32_t* oh = reinterpret_cast<uint32_t*>(g_wo_t + base);
            oh[0] = cvt_h2(w.x, w.y); oh[1] = cvt_h2(w.z, w.w);
        }
        return;
    }

    extern __shared__ char sm[];
    const uint32_t smb = smem_u32(sm);
    const int wid = tid >> 5, lane = tid & 31;
    const int g = lane >> 2, t = lane & 3;
    const int lm = lane >> 3, lr = lane & 7;
    const int bh = blockIdx.y;
    const int tile = blockIdx.x;
    const int n = bh >> 4, h = bh & 15;

    const float* xin = (z == 0) ? q_in : (z == 1) ? k_in : v_in;
    const float* W   = (z == 0) ? Wq   : (z == 1) ? Wk   : Wv;
    __half* outp     = (z == 0) ? g_qh : (z == 1) ? g_kh : g_vh;

    // ---- weight fp32 -> fp16 swizzled smem ----
#pragma unroll
    for (int u = 0; u < 2; u++) {
        int cl = tid + u * 256;
        int row = cl >> 3, c = cl & 7;
        float4 f0 = reinterpret_cast<const float4*>(W)[row * 16 + c * 2];
        float4 f1 = reinterpret_cast<const float4*>(W)[row * 16 + c * 2 + 1];
        uint4 pk;
        pk.x = cvt_h2(f0.x, f0.y); pk.y = cvt_h2(f0.z, f0.w);
        pk.z = cvt_h2(f1.x, f1.y); pk.w = cvt_h2(f1.z, f1.w);
        *reinterpret_cast<uint4*>(sm + row * 128 + ((c ^ (row & 7)) << 4)) = pk;
    }

    // ---- X tile fp32 -> fp16 swizzled smem ----
    const size_t inbase = ((size_t)n * LSEQ + tile * 256) * EMB + (size_t)h * HD;
#pragma unroll
    for (int u = 0; u < 8; u++) {
        int cl = tid + u * 256;
        int row = cl >> 3, c = cl & 7;
        const float4* src = reinterpret_cast<const float4*>(xin + inbase + (size_t)row * EMB);
        float4 f0 = src[c * 2], f1 = src[c * 2 + 1];
        uint4 pk;
        pk.x = cvt_h2(f0.x, f0.y); pk.y = cvt_h2(f0.z, f0.w);
        pk.z = cvt_h2(f1.x, f1.y); pk.w = cvt_h2(f1.z, f1.w);
        *reinterpret_cast<uint4*>(sm + 8192 + row * 128 + ((c ^ (row & 7)) << 4)) = pk;
    }
    __syncthreads();

    // ---- GEMM ----
    float c[2][8][4];
#pragma unroll
    for (int mi = 0; mi < 2; mi++)
#pragma unroll
        for (int ni = 0; ni < 8; ni++)
#pragma unroll
            for (int j = 0; j < 4; j++) c[mi][ni][j] = 0.f;

#pragma unroll
    for (int ks = 0; ks < 4; ks++) {
        uint32_t af[2][4];
#pragma unroll
        for (int mi = 0; mi < 2; mi++) {
            const int mrow = wid * 32 + mi * 16 + 8 * (lm & 1) + lr;
            const uint32_t addr = smb + 8192 + mrow * 128 +
                ((((ks << 1) | (lm >> 1)) ^ (mrow & 7)) << 4);
            LDMX4(af[mi][0], af[mi][1], af[mi][2], af[mi][3], addr);
        }
#pragma unroll
        for (int np = 0; np < 4; np++) {
            const int wrow = np * 16 + 8 * (lm >> 1) + lr;
            const uint32_t addr = smb + wrow * 128 +
                ((((ks << 1) | (lm & 1)) ^ (wrow & 7)) << 4);
            uint32_t bf[4];
            LDMX4(bf[0], bf[1], bf[2], bf[3], addr);
#pragma unroll
            for (int mi = 0; mi < 2; mi++) {
                mma16816h(c[mi][2*np],   af[mi], bf[0], bf[1]);
                mma16816h(c[mi][2*np+1], af[mi], bf[2], bf[3]);
            }
        }
    }

    // ---- epilogue: Q linear (scaled), K/V swizzled ----
    uint32_t* out32 = reinterpret_cast<uint32_t*>(outp);
    const int l0 = tile * 256 + wid * 32;
#pragma unroll
    for (int mi = 0; mi < 2; mi++) {
        const int l1 = l0 + mi * 16 + g, l2 = l1 + 8;
        const size_t r1 = ((size_t)bh * LSEQ + l1) * 32;
        const size_t r2 = ((size_t)bh * LSEQ + l2) * 32;
#pragma unroll
        for (int nt = 0; nt < 8; nt++) {
            float v0 = c[mi][nt][0], v1 = c[mi][nt][1];
            float v2 = c[mi][nt][2], v3 = c[mi][nt][3];
            if (z == 0) {
                out32[r1 + 4 * nt + t] = cvt_h2(v0 * QS, v1 * QS);
                out32[r2 + 4 * nt + t] = cvt_h2(v2 * QS, v3 * QS);
            } else {
                out32[r1 + (((nt ^ (l1 & 7)) << 2) | t)] = cvt_h2(v0, v1);
                out32[r2 + (((nt ^ (l2 & 7)) << 2) | t)] = cvt_h2(v2, v3);
            }
        }
    }
}

// ---------------------------------------------------------------------------
// Kernel 2: flash attention fp16, 128-key stages, 3-stage bulk pipeline.
// ---------------------------------------------------------------------------
#define ABUF 16384          // K: 128 keys x 128B
#define ASTG 32768          // K + V
#define SM_ATT 98328        // 3 stages + 3 mbars at +98304

__global__ void __launch_bounds__(256, 2) attn_kernel()
{
    extern __shared__ char sm[];
    const uint32_t smb = smem_u32(sm);
    const uint32_t mb[3] = {smb + 98304, smb + 98312, smb + 98320};
    const int tid = threadIdx.x, wid = tid >> 5, lane = tid & 31;
    const int g = lane >> 2, t = lane & 3;
    const int bh = blockIdx.y;
    const int q0 = blockIdx.x * 128;
    const int warp_q = q0 + wid * 16;

    const int lm = lane >> 3, lr = lane & 7;
    const int kcb = lm & 1;
    const uint32_t krb = (uint32_t)((8 * (lm >> 1) + lr) * 128);
    const int vcb = lm >> 1;
    const uint32_t vrb = (uint32_t)(((lm & 1) * 8 + lr) * 128);

    if (tid == 0) { MBAR_INIT(mb[0], 1); MBAR_INIT(mb[1], 1); MBAR_INIT(mb[2], 1); }
    __syncthreads();

    uint32_t qh[4][4];
    {
        const uint32_t* bhp = reinterpret_cast<const uint32_t*>(g_qh) + ((size_t)bh * LSEQ + warp_q) * 32;
#pragma unroll
        for (int ks = 0; ks < 4; ks++) {
            qh[ks][0] = bhp[(size_t)g * 32 + 8*ks + t];
            qh[ks][1] = bhp[(size_t)(g+8) * 32 + 8*ks + t];
            qh[ks][2] = bhp[(size_t)g * 32 + 8*ks + t + 4];
            qh[ks][3] = bhp[(size_t)(g+8) * 32 + 8*ks + t + 4];
        }
    }

    auto issue_stage = [&](int kt, int s) {
        const uint32_t sb = smb + s * ASTG;
        const size_t go = ((size_t)bh * LSEQ + kt * 128) * HD;
        MBAR_EXPECT_TX(mb[s], 2 * ABUF);
        CP_BULK(sb,            (const char*)g_kh + go * 2, ABUF, mb[s]);
        CP_BULK(sb + ABUF,     (const char*)g_vh + go * 2, ABUF, mb[s]);
    };

    float o[8][4];
#pragma unroll
    for (int i = 0; i < 8; i++)
#pragma unroll
        for (int j = 0; j < 4; j++) o[i][j] = 0.f;
    float lsacc[4] = {0.f, 0.f, 0.f, 0.f};

    if (tid == 0) { issue_stage(0, 0); issue_stage(1, 1); }

    for (int kt = 0; kt < 16; kt++) {
        const int s = kt % 3;
        if (kt < 14 && tid == 0) issue_stage(kt + 2, (kt + 2) % 3);
        MBAR_WAIT(mb[s], (kt / 3) & 1);

        const uint32_t KHb = smb + s * ASTG;
        const uint32_t VHb = KHb + ABUF;

#pragma unroll
        for (int qtr = 0; qtr < 4; qtr++) {
            const uint32_t hoff = qtr * 4096;   // 32 key rows

            float sc[4][4];
#pragma unroll
            for (int nt = 0; nt < 4; nt++)
#pragma unroll
                for (int j = 0; j < 4; j++) sc[nt][j] = 0.f;

#pragma unroll
            for (int ks = 0; ks < 4; ks++) {
                const uint32_t csw = (uint32_t)((((ks << 1) | kcb) ^ lr) << 4);
                uint32_t kf[8];
                LDMX4(kf[0], kf[1], kf[2], kf[3], KHb + hoff + krb + csw);
                LDMX4(kf[4], kf[5], kf[6], kf[7], KHb + hoff + 2048 + krb + csw);
#pragma unroll
                for (int nt = 0; nt < 4; nt++)
                    mma16816h(sc[nt], qh[ks], kf[2*nt], kf[2*nt+1]);
            }

            uint32_t ph[2][4];
#pragma unroll
            for (int nt = 0; nt < 4; nt++) {
                const int kc = nt >> 1, su = (nt & 1) * 2;
                ph[kc][su + 0] = ex2_h2(cvt_h2(sc[nt][0], sc[nt][1]));
                ph[kc][su + 1] = ex2_h2(cvt_h2(sc[nt][2], sc[nt][3]));
            }

#pragma unroll
            for (int kc = 0; kc < 2; kc++) {
                const uint32_t kb = hoff + kc * 2048;
#pragma unroll
                for (int db = 0; db < 4; db++) {
                    const uint32_t csw = (uint32_t)((((db << 1) | vcb) ^ lr) << 4);
                    uint32_t vhf[4];
                    LDMX4T(vhf[0], vhf[1], vhf[2], vhf[3], VHb + kb + vrb + csw);
                    mma16816h(o[2*db],   ph[kc], vhf[0], vhf[1]);
                    mma16816h(o[2*db+1], ph[kc], vhf[2], vhf[3]);
                }
                mma16816h(lsacc, ph[kc], HONES, HONES);
            }
        }
        __syncthreads();
    }

    const float inv0 = 1.f / lsacc[0], inv1 = 1.f / lsacc[2];

    const int n = bh >> 4, h = bh & 15;
    const int gt1 = n * LSEQ + warp_q + g;
    const int gt2 = gt1 + 8;
    const int mb1 = gt1 >> 7, mr1 = gt1 & 127;
    const int mb2 = gt2 >> 7, mr2 = gt2 & 127;
#pragma unroll
    for (int nd = 0; nd < 8; nd++) {
        const int dcol = 8 * nd + 2 * t;
        const int kb = h * 2 + (dcol >> 5);
        const int c = dcol & 31;
        const size_t i1 = (((size_t)(mb1 * 32 + kb) * 128 + mr1) * 40 + c) >> 1;
        const size_t i2 = (((size_t)(mb2 * 32 + kb) * 128 + mr2) * 40 + c) >> 1;
        reinterpret_cast<uint32_t*>(g_ao_t)[i1] = cvt_h2(o[nd][0] * inv0, o[nd][1] * inv0);
        reinterpret_cast<uint32_t*>(g_ao_t)[i2] = cvt_h2(o[nd][2] * inv1, o[nd][3] * inv1);
    }
}

// ---------------------------------------------------------------------------
// Kernel 3: output projection, 64-k stages (2 kb per bulk copy), 2-stage.
// ---------------------------------------------------------------------------
#define OSTRB 80
#define OKB   10240         // one kb tile (128 x 40 half)
#define OSTG  40960         // stage: A (2 kb) + W (2 kb)
#define SM_GEMM 81936       // 2 stages + 2 mbars at +81920

__global__ void __launch_bounds__(256, 2) out_proj_kernel(
    const float* __restrict__ bias, float* __restrict__ C)
{
    extern __shared__ char sm[];
    const uint32_t smb = smem_u32(sm);
    const uint32_t mb[2] = {smb + 81920, smb + 81928};
    const int tid = threadIdx.x, wid = tid >> 5, lane = tid & 31;
    const int g = lane >> 2, t = lane & 3;
    const int lm = lane >> 3, lr = lane & 7;
    const int m0 = blockIdx.y * 128;
    const int n0 = blockIdx.x * 128;
    const int wm = (wid & 3) * 32;
    const int wn = (wid >> 2) * 64;

    const uint32_t a_lmo = (uint32_t)(((lm & 1) * 8 + lr) * OSTRB + (lm >> 1) * 16);
    const uint32_t b_lmo = (uint32_t)(((lm >> 1) * 8 + lr) * OSTRB + (lm & 1) * 16);

    if (tid == 0) { MBAR_INIT(mb[0], 1); MBAR_INIT(mb[1], 1); }
    __syncthreads();

    auto issue_stage = [&](int kt, int s) {   // kt in 64-k units
        const uint32_t sb = smb + s * OSTG;
        const size_t ao = (size_t)(blockIdx.y * 32 + kt * 2) * (128 * 40);
        const size_t wo = (size_t)(blockIdx.x * 32 + kt * 2) * (128 * 40);
        MBAR_EXPECT_TX(mb[s], 2 * 2 * OKB);
        CP_BULK(sb,            (const char*)g_ao_t + ao * 2, 2 * OKB, mb[s]);
        CP_BULK(sb + 2 * OKB,  (const char*)g_wo_t + wo * 2, 2 * OKB, mb[s]);
    };

    float acc[2][8][4];
#pragma unroll
    for (int i = 0; i < 2; i++)
#pragma unroll
        for (int j = 0; j < 8; j++)
#pragma unroll
            for (int k = 0; k < 4; k++) acc[i][j][k] = 0.f;

    if (tid == 0) issue_stage(0, 0);

    for (int kt = 0; kt < 16; kt++) {
        const int s = kt & 1;
        if (kt < 15 && tid == 0) issue_stage(kt + 1, s ^ 1);
        MBAR_WAIT(mb[s], (kt >> 1) & 1);

        const uint32_t Ao = smb + s * OSTG;
        const uint32_t Bo = Ao + 2 * OKB;

#pragma unroll
        for (int kq = 0; kq < 2; kq++) {       // which kb tile within stage
            const uint32_t ko = kq * OKB;
#pragma unroll
            for (int ks = 0; ks < 2; ks++) {
                uint32_t ah[2][4];
#pragma unroll
                for (int mi = 0; mi < 2; mi++)
                    LDMX4(ah[mi][0], ah[mi][1], ah[mi][2], ah[mi][3],
                          Ao + ko + (wm + mi * 16) * OSTRB + ks * 32 + a_lmo);
#pragma unroll
                for (int ni = 0; ni < 8; ni += 2) {
                    uint32_t bf[4];
                    LDMX4(bf[0], bf[1], bf[2], bf[3],
                          Bo + ko + (wn + ni * 8) * OSTRB + ks * 32 + b_lmo);
#pragma unroll
                    for (int mi = 0; mi < 2; mi++) {
                        mma16816h(acc[mi][ni],     ah[mi], bf[0], bf[1]);
                        mma16816h(acc[mi][ni + 1], ah[mi], bf[2], bf[3]);
                    }
                }
            }
        }
        __syncthreads();
    }

#pragma unroll
    for (int mi = 0; mi < 2; mi++) {
        const int r1 = m0 + wm + mi * 16 + g;
        const int r2 = r1 + 8;
#pragma unroll
        for (int ni = 0; ni < 8; ni++) {
            const int col = n0 + wn + ni * 8 + 2 * t;
            float2 bv = *reinterpret_cast<const float2*>(bias + col);
            *reinterpret_cast<float2*>(C + (size_t)r1 * EMB + col) =
                make_float2(acc[mi][ni][0] + bv.x, acc[mi][ni][1] + bv.y);
            *reinterpret_cast<float2*>(C + (size_t)r2 * EMB + col) =
                make_float2(acc[mi][ni][2] + bv.x, acc[mi][ni][3] + bv.y);
        }
    }
}

// ---------------------------------------------------------------------------
extern "C" void kernel_launch(void* const* d_in, const int* in_sizes, int n_in,
                              void* d_out, int out_size)
{
    const float* values  = (const float*)d_in[0];
    const float* keys    = (const float*)d_in[1];
    const float* queries = (const float*)d_in[2];
    const float* Wv      = (const float*)d_in[3];
    const float* Wk      = (const float*)d_in[4];
    const float* Wq      = (const float*)d_in[5];
    const float* Wo      = (const float*)d_in[6];
    const float* bo      = (const float*)d_in[7];
    float* out = (float*)d_out;

    static bool attr_set = false;
    if (!attr_set) {
        cudaFuncSetAttribute(qkv_mma_kernel,
                             cudaFuncAttributeMaxDynamicSharedMemorySize, QKV_SM);
        cudaFuncSetAttribute(attn_kernel,
                             cudaFuncAttributeMaxDynamicSharedMemorySize, SM_ATT);
        cudaFuncSetAttribute(out_proj_kernel,
                             cudaFuncAttributeMaxDynamicSharedMemorySize, SM_GEMM);
        attr_set = true;
    }

    dim3 g1(LSEQ / 256, BHN, 4);   // z: 0=q, 1=k, 2=v, 3=Wo tiling
    qkv_mma_kernel<<<g1, 256, QKV_SM>>>(queries, keys, values, Wq, Wk, Wv, Wo);

    dim3 g2(LSEQ / 128, BHN);
    attn_kernel<<<g2, 256, SM_ATT>>>();

    dim3 g3(EMB / 128, (NB * LSEQ) / 128);
    out_proj_kernel<<<g3, 256, SM_GEMM>>>(bo, out);
}